// round 3
// baseline (speedup 1.0000x reference)
#include <cuda_runtime.h>
#include <math.h>
#include <stdint.h>

// Problem constants
#define Tt   4
#define Bb   4
#define Nn   16384
#define KALLc 4
#define Ff   16384
#define ORD  3
#define Hh   64
#define N0c  4096

#define TBc  (Tt*Bb)        // 16
#define BNc  (Bb*Nn)        // 65536
#define TBNc (TBc*Nn)       // 262144
#define H3c  (3*Hh)         // 192

// Output layout: h_fin [B,N,H] | h_global [B,K,64] | logit [T,B,N] | value [T,B]
#define OFF_HG    4194304
#define OFF_LOGIT (OFF_HG + 1024)
#define OFF_VAL   (OFF_LOGIT + 262144)

// Scratch
__device__ float g_qkv[TBNc * H3c];   // [T,B,N,192]
__device__ float g_yo [TBNc * Hh];    // [T,B,N,64] scatter-sum of attention o
__device__ int   g_cnt[Nn];
__device__ float g_M  [64*64];        // Wo @ W1[:64]
__device__ float g_c1 [64];           // bo @ W1[:64]
__device__ float g_E  [64*64];        // per (tb,kall): b1 + extra@W1[64:]
__device__ float g_wv [64];           // Wo @ Wv1[:64]
__device__ float g_bv [1];            // bo @ Wv1[:64]
__device__ float g_s1 [64*64];        // per (tb,kall): sum_n yo*invnnz
__device__ float g_s0 [64];           // per (tb,kall): sum_n cnt*invnnz

__device__ __forceinline__ float sigmoidf_(float v) { return 1.f / (1.f + expf(-v)); }
__device__ __forceinline__ void fma4_(float4& a, float s, float4 w) {
    a.x += s * w.x; a.y += s * w.y; a.z += s * w.z; a.w += s * w.w;
}

// ---------------------------------------------------------------------------
__global__ void k_count(const int* __restrict__ indices) {
    int i = blockIdx.x * 256 + threadIdx.x;
    if (i < Ff * ORD) atomicAdd(&g_cnt[indices[i]], 1);
}

// ---------------------------------------------------------------------------
// Prep: fold Wo into W1 / Wv1 and bake the extra/bias constants.
// ---------------------------------------------------------------------------
__global__ void k_prep(const float* __restrict__ Wo, const float* __restrict__ bo,
                       const float* __restrict__ W1, const float* __restrict__ b1,
                       const float* __restrict__ Wv1,
                       const float* __restrict__ extra)
{
    int tid = threadIdx.x;   // 256 threads
    // M[j][c] = sum_h Wo[j*64+h] * W1[h*64+c]
    for (int o = tid; o < 4096; o += 256) {
        int j = o >> 6, c = o & 63;
        float s = 0.f;
        #pragma unroll
        for (int h = 0; h < 64; h++) s += Wo[j*64 + h] * W1[h*64 + c];
        g_M[o] = s;
    }
    // c1[c] = sum_h bo[h]*W1[h*64+c]
    if (tid < 64) {
        float s = 0.f;
        #pragma unroll
        for (int h = 0; h < 64; h++) s += bo[h] * W1[h*64 + tid];
        g_c1[tid] = s;
    }
    // E[g][c] = b1[c] + sum_d extra[g*4+d]*W1[(64+d)*64+c]
    for (int o = tid; o < 4096; o += 256) {
        int g = o >> 6, c = o & 63;
        float s = b1[c];
        #pragma unroll
        for (int d = 0; d < 4; d++) s += extra[g*4 + d] * W1[(64 + d)*64 + c];
        g_E[o] = s;
    }
    // wo_v[j] = sum_h Wo[j*64+h]*Wv1[h]; bo_v = sum_h bo[h]*Wv1[h]
    if (tid < 64) {
        float s = 0.f;
        #pragma unroll
        for (int h = 0; h < 64; h++) s += Wo[tid*64 + h] * Wv1[h];
        g_wv[tid] = s;
    }
    if (tid == 0) {
        float s = 0.f;
        #pragma unroll
        for (int h = 0; h < 64; h++) s += bo[h] * Wv1[h];
        g_bv[0] = s;
    }
}

// ---------------------------------------------------------------------------
// Fused GRU scan (T=4) + per-step QKV projection (unchanged from R1).
// ---------------------------------------------------------------------------
__global__ __launch_bounds__(128)
void k_gru_qkv(const float* __restrict__ h0, const float* __restrict__ x,
               const uint32_t* __restrict__ dones,
               const float* __restrict__ Wi, const float* __restrict__ bi,
               const float* __restrict__ Wh, const float* __restrict__ bhn,
               const float* __restrict__ Wq, const float* __restrict__ bq,
               const float* __restrict__ Wk, const float* __restrict__ bk,
               const float* __restrict__ Wv, const float* __restrict__ bv,
               float* __restrict__ hfin_out)
{
    extern __shared__ float smem[];
    float* sWh   = smem;              // 12288
    float* sWi   = sWh + 12288;       // 768
    float* sWqkv = sWi + 768;         // 12288
    float* sbi   = sWqkv + 12288;     // 192
    float* sbqkv = sbi + 192;         // 192
    float* sbhn  = sbqkv + 192;       // 64

    for (int i = threadIdx.x; i < 12288; i += 128) sWh[i] = Wh[i];
    for (int i = threadIdx.x; i < 768;   i += 128) sWi[i] = Wi[i];
    for (int i = threadIdx.x; i < 12288; i += 128) {
        int j = i / 192, e = i % 192;
        sWqkv[i] = (e < 64) ? Wq[j*64 + e] : (e < 128) ? Wk[j*64 + e - 64] : Wv[j*64 + e - 128];
    }
    for (int i = threadIdx.x; i < 192; i += 128) sbi[i] = bi[i];
    for (int i = threadIdx.x; i < 192; i += 128)
        sbqkv[i] = (i < 64) ? bq[i] : (i < 128) ? bk[i - 64] : bv[i - 128];
    for (int i = threadIdx.x; i < 64; i += 128) sbhn[i] = bhn[i];
    __syncthreads();

    const float4* sWh4   = (const float4*)sWh;
    const float4* sWi4   = (const float4*)sWi;
    const float4* sWqkv4 = (const float4*)sWqkv;
    const float4* sbi4   = (const float4*)sbi;
    const float4* sbqkv4 = (const float4*)sbqkv;
    const float4* sbhn4  = (const float4*)sbhn;

    int gid = blockIdx.x * 128 + threadIdx.x;
    int b = gid >> 14;

    float h[64];
    {
        const float4* h04 = (const float4*)(h0 + (size_t)gid * 64);
        #pragma unroll
        for (int j = 0; j < 16; j++) {
            float4 v = h04[j];
            h[4*j] = v.x; h[4*j+1] = v.y; h[4*j+2] = v.z; h[4*j+3] = v.w;
        }
    }

    #pragma unroll 1
    for (int t = 0; t < Tt; t++) {
        if (dones[t * Bb + b] != 0u) {
            #pragma unroll
            for (int j = 0; j < 64; j++) h[j] = 0.f;
        }
        float4 xt4 = ((const float4*)x)[(size_t)t * BNc + gid];
        float xt[4] = {xt4.x, xt4.y, xt4.z, xt4.w};

        float hn[64];
        #pragma unroll
        for (int kk = 0; kk < 16; kk++) {
            float4 ar = {0,0,0,0}, az = {0,0,0,0}, an = {0,0,0,0};
            #pragma unroll
            for (int j = 0; j < 64; j++) {
                float hj = h[j];
                fma4_(ar, hj, sWh4[j*48 + kk]);
                fma4_(az, hj, sWh4[j*48 + 16 + kk]);
                fma4_(an, hj, sWh4[j*48 + 32 + kk]);
            }
            float4 gr = sbi4[kk], gz = sbi4[16 + kk], gn = sbi4[32 + kk];
            #pragma unroll
            for (int d = 0; d < 4; d++) {
                float xd = xt[d];
                fma4_(gr, xd, sWi4[d*48 + kk]);
                fma4_(gz, xd, sWi4[d*48 + 16 + kk]);
                fma4_(gn, xd, sWi4[d*48 + 32 + kk]);
            }
            float4 bn4 = sbhn4[kk];
            float r, z, nv;
            r = sigmoidf_(gr.x + ar.x); z = sigmoidf_(gz.x + az.x);
            nv = tanhf(gn.x + r * (an.x + bn4.x));
            hn[4*kk+0] = (1.f - z) * nv + z * h[4*kk+0];
            r = sigmoidf_(gr.y + ar.y); z = sigmoidf_(gz.y + az.y);
            nv = tanhf(gn.y + r * (an.y + bn4.y));
            hn[4*kk+1] = (1.f - z) * nv + z * h[4*kk+1];
            r = sigmoidf_(gr.z + ar.z); z = sigmoidf_(gz.z + az.z);
            nv = tanhf(gn.z + r * (an.z + bn4.z));
            hn[4*kk+2] = (1.f - z) * nv + z * h[4*kk+2];
            r = sigmoidf_(gr.w + ar.w); z = sigmoidf_(gz.w + az.w);
            nv = tanhf(gn.w + r * (an.w + bn4.w));
            hn[4*kk+3] = (1.f - z) * nv + z * h[4*kk+3];
        }
        #pragma unroll
        for (int j = 0; j < 64; j++) h[j] = hn[j];

        float4* out = (float4*)(g_qkv + ((size_t)t * BNc + gid) * H3c);
        #pragma unroll 1
        for (int kk = 0; kk < 48; kk++) {
            float4 acc = sbqkv4[kk];
            #pragma unroll
            for (int j = 0; j < 64; j++) fma4_(acc, h[j], sWqkv4[j*48 + kk]);
            out[kk] = acc;
        }
    }

    float4* ho = (float4*)(hfin_out + (size_t)gid * 64);
    #pragma unroll
    for (int j = 0; j < 16; j++) {
        float4 v = {h[4*j], h[4*j+1], h[4*j+2], h[4*j+3]};
        ho[j] = v;
    }
}

// ---------------------------------------------------------------------------
// Attention per (t,b,f) (unchanged from R1).
// ---------------------------------------------------------------------------
__global__ __launch_bounds__(256)
void k_attn(const int* __restrict__ indices)
{
    __shared__ __align__(16) float sR[8][3][192];
    __shared__ __align__(16) float sO[8][3][64];

    int warp = threadIdx.x >> 5, lane = threadIdx.x & 31;
    int inst = blockIdx.x * 8 + warp;
    int tb = inst >> 14;
    int f  = inst & 16383;

    int idx[3] = {__ldg(&indices[f*3]), __ldg(&indices[f*3+1]), __ldg(&indices[f*3+2])};

    const float* base = g_qkv + (size_t)tb * Nn * H3c;
    #pragma unroll
    for (int k = 0; k < 3; k++) {
        const float* row = base + (size_t)idx[k] * H3c;
        #pragma unroll
        for (int u = 0; u < 6; u++) sR[warp][k][u*32 + lane] = row[u*32 + lane];
    }
    __syncwarp();

    if (lane < 12) {
        int qr = lane >> 2, hh = lane & 3;
        const float* q = &sR[warp][qr][hh * 16];
        float l[3];
        #pragma unroll
        for (int kr = 0; kr < 3; kr++) {
            const float* kv = &sR[warp][kr][64 + hh * 16];
            float s = 0.f;
            #pragma unroll
            for (int d = 0; d < 16; d++) s += q[d] * kv[d];
            l[kr] = s * 0.25f;
        }
        float m = fmaxf(l[0], fmaxf(l[1], l[2]));
        float e0 = expf(l[0] - m), e1 = expf(l[1] - m), e2 = expf(l[2] - m);
        float inv = 1.f / (e0 + e1 + e2);
        e0 *= inv; e1 *= inv; e2 *= inv;
        const float* v0 = &sR[warp][0][128 + hh * 16];
        const float* v1 = &sR[warp][1][128 + hh * 16];
        const float* v2 = &sR[warp][2][128 + hh * 16];
        #pragma unroll
        for (int d = 0; d < 16; d++)
            sO[warp][qr][hh*16 + d] = e0 * v0[d] + e1 * v1[d] + e2 * v2[d];
    }
    __syncwarp();

    float4* yo = (float4*)g_yo + (size_t)tb * Nn * 16;
    if (lane < 16) {
        #pragma unroll
        for (int k = 0; k < 3; k++) {
            float4 v = ((const float4*)sO[warp][k])[lane];
            atomicAdd(&yo[(size_t)idx[k] * 16 + lane], v);
        }
    }
}

// ---------------------------------------------------------------------------
// Segment sums for the value head: per (tb,kall) g: s1 = sum_n yo*invnnz,
// s0 = sum_n cnt*invnnz. Coalesced full re-read of g_yo (67MB, ~10us).
// ---------------------------------------------------------------------------
__global__ __launch_bounds__(256)
void k_sum(const float* __restrict__ nnz)
{
    __shared__ float red[4][64];
    __shared__ float red0[4];
    int g = blockIdx.x;          // 0..63
    int tid = threadIdx.x;
    int r4 = tid >> 6;           // 0..3
    int col = tid & 63;

    float acc = 0.f, acc0 = 0.f;
    int nbase = (g & 3) * 4096;
    const float* yob = g_yo + (size_t)g * 4096 * 64;
    for (int rr = r4; rr < 4096; rr += 4) {
        int n = nbase + rr;
        float inv = 1.f / nnz[n];
        acc += yob[(size_t)rr * 64 + col] * inv;
        if (col == 0) acc0 += (float)g_cnt[n] * inv;
    }
    red[r4][col] = acc;
    if (col == 0) red0[r4] = acc0;
    __syncthreads();
    if (tid < 64)
        g_s1[g * 64 + tid] = red[0][tid] + red[1][tid] + red[2][tid] + red[3][tid];
    if (tid == 0)
        g_s0[g] = red0[0] + red0[1] + red0[2] + red0[3];
}

// ---------------------------------------------------------------------------
// Logit head (rewritten): one thread per row.
// pre[c] = invnnz*(yo . M[:,c]) + cn*invnnz*c1[c] + E[g][c]
// logit  = sum_c relu(pre[c])*W2[c] + b2
// yo row in registers (staged via padded shared tile), M broadcast LDS.128.
// ---------------------------------------------------------------------------
__global__ __launch_bounds__(256, 2)
void k_post(const float* __restrict__ nnz,
            const float* __restrict__ W2, const float* __restrict__ b2,
            float* __restrict__ logit_out)
{
    extern __shared__ float ps[];
    float4* sT4 = (float4*)ps;                 // 256 rows x 17 float4 (pad) = 69632B
    float*  sM  = ps + 256*17*4;               // 4096 floats
    float*  sc1 = sM + 4096;                   // 64
    float*  sE  = sc1 + 64;                    // 64
    float*  sW2 = sE + 64;                     // 64

    int tid = threadIdx.x;
    int rowbase = blockIdx.x * 256;
    int g = rowbase >> 12;                     // same for whole block

    // stage yo tile (coalesced float4)
    const float4* yo4 = (const float4*)g_yo + (size_t)rowbase * 16;
    for (int i = tid; i < 4096; i += 256)
        sT4[(i >> 4) * 17 + (i & 15)] = yo4[i];
    for (int i = tid; i < 4096; i += 256) sM[i] = g_M[i];
    if (tid < 64) { sc1[tid] = g_c1[tid]; sE[tid] = g_E[g*64 + tid]; sW2[tid] = W2[tid]; }
    __syncthreads();

    int row = rowbase + tid;
    int n = row & 16383;
    float inv = 1.f / nnz[n];
    float cninv = (float)g_cnt[n] * inv;

    // own row into registers (conflict-free: stride 17 float4, 17 coprime 32)
    float yo[64];
    #pragma unroll
    for (int jj = 0; jj < 16; jj++) {
        float4 v = sT4[tid * 17 + jj];
        yo[4*jj] = v.x; yo[4*jj+1] = v.y; yo[4*jj+2] = v.z; yo[4*jj+3] = v.w;
    }

    const float4* sM4 = (const float4*)sM;
    float logit = 0.f;
    #pragma unroll
    for (int p = 0; p < 2; p++) {              // two passes of 32 outputs
        float4 acc[8];
        #pragma unroll
        for (int kk = 0; kk < 8; kk++) acc[kk] = make_float4(0.f, 0.f, 0.f, 0.f);
        #pragma unroll
        for (int j = 0; j < 64; j++) {
            float yj = yo[j];
            #pragma unroll
            for (int kk = 0; kk < 8; kk++)
                fma4_(acc[kk], yj, sM4[j*16 + p*8 + kk]);
        }
        #pragma unroll
        for (int kk = 0; kk < 8; kk++) {
            int c = p*32 + kk*4;
            float pre, r;
            pre = inv*acc[kk].x + cninv*sc1[c]   + sE[c];   r = fmaxf(pre,0.f); logit += r*sW2[c];
            pre = inv*acc[kk].y + cninv*sc1[c+1] + sE[c+1]; r = fmaxf(pre,0.f); logit += r*sW2[c+1];
            pre = inv*acc[kk].z + cninv*sc1[c+2] + sE[c+2]; r = fmaxf(pre,0.f); logit += r*sW2[c+2];
            pre = inv*acc[kk].w + cninv*sc1[c+3] + sE[c+3]; r = fmaxf(pre,0.f); logit += r*sW2[c+3];
        }
    }
    logit_out[row] = logit + b2[0];
}

// ---------------------------------------------------------------------------
// Value head: value[tb] = sum_kall ( (s1.wo_v + s0*bo_v)/N0 + extra.Wv1b + bv1 )
// ---------------------------------------------------------------------------
__global__ void k_value(const float* __restrict__ extra,
                        const float* __restrict__ Wv1, const float* __restrict__ bv1,
                        float* __restrict__ val_out)
{
    __shared__ float sv[64];
    int tid = threadIdx.x;                  // 64 = (tb,kall)
    float acc = 0.f;
    #pragma unroll
    for (int j = 0; j < 64; j++) acc += g_s1[tid*64 + j] * g_wv[j];
    acc += g_s0[tid] * g_bv[0];
    acc *= (1.f / (float)N0c);
    #pragma unroll
    for (int d = 0; d < 4; d++) acc += extra[tid*4 + d] * Wv1[64 + d];
    acc += bv1[0];
    sv[tid] = acc;
    __syncthreads();
    if (tid < 16)
        val_out[tid] = sv[tid*4] + sv[tid*4+1] + sv[tid*4+2] + sv[tid*4+3];
}

// ---------------------------------------------------------------------------
extern "C" void kernel_launch(void* const* d_in, const int* in_sizes, int n_in,
                              void* d_out, int out_size)
{
    const float* h0       = (const float*)d_in[0];
    const float* h_global = (const float*)d_in[1];
    const float* x        = (const float*)d_in[2];
    const float* extra    = (const float*)d_in[3];
    const uint32_t* dones = (const uint32_t*)d_in[4];
    const int*   indices  = (const int*)d_in[5];
    const float* nnz      = (const float*)d_in[6];
    const float* Wi  = (const float*)d_in[7];
    const float* bi  = (const float*)d_in[8];
    const float* Wh  = (const float*)d_in[9];
    const float* bhn = (const float*)d_in[10];
    const float* Wq  = (const float*)d_in[11];
    const float* bq  = (const float*)d_in[12];
    const float* Wk  = (const float*)d_in[13];
    const float* bk  = (const float*)d_in[14];
    const float* Wv  = (const float*)d_in[15];
    const float* bv  = (const float*)d_in[16];
    const float* Wo  = (const float*)d_in[17];
    const float* bo  = (const float*)d_in[18];
    const float* W1  = (const float*)d_in[19];
    const float* b1  = (const float*)d_in[20];
    const float* W2  = (const float*)d_in[21];
    const float* b2  = (const float*)d_in[22];
    const float* Wv1 = (const float*)d_in[23];
    const float* bv1 = (const float*)d_in[24];

    float* out       = (float*)d_out;
    float* out_hfin  = out;
    float* out_hg    = out + OFF_HG;
    float* out_logit = out + OFF_LOGIT;
    float* out_val   = out + OFF_VAL;

    void *yo_ptr, *cnt_ptr;
    cudaGetSymbolAddress(&yo_ptr,  g_yo);
    cudaGetSymbolAddress(&cnt_ptr, g_cnt);
    cudaMemsetAsync(yo_ptr,  0, sizeof(float) * (size_t)TBNc * Hh, 0);
    cudaMemsetAsync(cnt_ptr, 0, sizeof(int) * Nn, 0);

    cudaMemcpyAsync(out_hg, h_global, 1024 * sizeof(float), cudaMemcpyDeviceToDevice, 0);

    int smem_gru = (12288 + 768 + 12288 + 192 + 192 + 64) * 4;   // 103168 B
    cudaFuncSetAttribute(k_gru_qkv, cudaFuncAttributeMaxDynamicSharedMemorySize, smem_gru);
    int smem_post = (256*17*4 + 4096 + 64 + 64 + 64) * 4;         // 87040 B
    cudaFuncSetAttribute(k_post, cudaFuncAttributeMaxDynamicSharedMemorySize, smem_post);

    k_count<<<(Ff * ORD + 255) / 256, 256>>>(indices);
    k_prep<<<1, 256>>>(Wo, bo, W1, b1, Wv1, extra);
    k_gru_qkv<<<BNc / 128, 128, smem_gru>>>(h0, x, dones, Wi, bi, Wh, bhn,
                                            Wq, bq, Wk, bk, Wv, bv, out_hfin);
    k_attn<<<TBc * Ff / 8, 256>>>(indices);
    k_sum<<<64, 256>>>(nnz);
    k_post<<<TBNc / 256, 256, smem_post>>>(nnz, W2, b2, out_logit);
    k_value<<<1, 64>>>(extra, Wv1, bv1, out_val);
}

// round 4
// speedup vs baseline: 1.3144x; 1.3144x over previous
#include <cuda_runtime.h>
#include <math.h>
#include <stdint.h>

// Problem constants
#define Tt   4
#define Bb   4
#define Nn   16384
#define KALLc 4
#define Ff   16384
#define ORD  3
#define Hh   64
#define N0c  4096

#define TBc  (Tt*Bb)        // 16
#define BNc  (Bb*Nn)        // 65536
#define TBNc (TBc*Nn)       // 262144
#define H3c  (3*Hh)         // 192

// Output layout: h_fin [B,N,H] | h_global [B,K,64] | logit [T,B,N] | value [T,B]
#define OFF_HG    4194304
#define OFF_LOGIT (OFF_HG + 1024)
#define OFF_VAL   (OFF_LOGIT + 262144)

// Scratch
__device__ float g_qkv[TBNc * H3c];   // [T,B,N,192]
__device__ float g_yo [TBNc * Hh];    // [T,B,N,64]
__device__ int   g_cnt[Nn];
__device__ float g_M  [64*64];        // Wo @ W1[:64]
__device__ float g_c1 [64];           // bo @ W1[:64]
__device__ float g_E  [64*64];        // per (tb,kall): b1 + extra@W1[64:]
__device__ float g_wv [64];           // Wo @ Wv1[:64]
__device__ float g_bv [1];            // bo @ Wv1[:64]
__device__ float g_s1 [64*64];        // per (tb,kall): sum_n yo*invnnz
__device__ float g_s0 [64];           // per (tb,kall): sum_n cnt*invnnz

__device__ __forceinline__ float sigmoidf_(float v) { return 1.f / (1.f + expf(-v)); }
__device__ __forceinline__ void fma4_(float4& a, float s, float4 w) {
    a.x += s * w.x; a.y += s * w.y; a.z += s * w.z; a.w += s * w.w;
}

// ---- packed fp32 helpers (fma.rn.f32x2: ptxas never emits FFMA2 on its own) ----
__device__ __forceinline__ unsigned long long packdup(float v) {
    unsigned long long r;
    asm("mov.b64 %0, {%1, %1};" : "=l"(r) : "f"(v));
    return r;
}
__device__ __forceinline__ unsigned long long pack2(float a, float b) {
    unsigned long long r;
    asm("mov.b64 %0, {%1, %2};" : "=l"(r) : "f"(a), "f"(b));
    return r;
}
__device__ __forceinline__ void ffma2(unsigned long long& acc,
                                      unsigned long long a, unsigned long long b) {
    asm("fma.rn.f32x2 %0, %1, %2, %0;" : "+l"(acc) : "l"(a), "l"(b));
}
__device__ __forceinline__ float2 unpack2(unsigned long long v) {
    float lo, hi;
    asm("mov.b64 {%0, %1}, %2;" : "=f"(lo), "=f"(hi) : "l"(v));
    return make_float2(lo, hi);
}

// ---------------------------------------------------------------------------
__global__ void k_count(const int* __restrict__ indices) {
    int i = blockIdx.x * 256 + threadIdx.x;
    if (i < Ff * ORD) atomicAdd(&g_cnt[indices[i]], 1);
}

// ---------------------------------------------------------------------------
// Prep (parallelized): fold Wo into W1 / Wv1 and bake extra/bias constants.
// ---------------------------------------------------------------------------
__global__ void k_prep(const float* __restrict__ Wo, const float* __restrict__ bo,
                       const float* __restrict__ W1, const float* __restrict__ b1,
                       const float* __restrict__ Wv1,
                       const float* __restrict__ extra)
{
    int o = blockIdx.x * 256 + threadIdx.x;   // grid 32 x 256 = 8192
    if (o < 4096) {
        int j = o >> 6, c = o & 63;
        float s = 0.f;
        #pragma unroll
        for (int h = 0; h < 64; h++) s += Wo[j*64 + h] * W1[h*64 + c];
        g_M[o] = s;
    } else {
        int e = o - 4096;
        int g = e >> 6, c = e & 63;
        float s = b1[c];
        #pragma unroll
        for (int d = 0; d < 4; d++) s += extra[g*4 + d] * W1[(64 + d)*64 + c];
        g_E[e] = s;
    }
    if (blockIdx.x == 0 && threadIdx.x < 64) {
        int tid = threadIdx.x;
        float s = 0.f, w = 0.f;
        #pragma unroll
        for (int h = 0; h < 64; h++) {
            s += bo[h] * W1[h*64 + tid];
            w += Wo[tid*64 + h] * Wv1[h];
        }
        g_c1[tid] = s;
        g_wv[tid] = w;
        if (tid == 0) {
            float bvv = 0.f;
            #pragma unroll
            for (int h = 0; h < 64; h++) bvv += bo[h] * Wv1[h];
            g_bv[0] = bvv;
        }
    }
}

// ---------------------------------------------------------------------------
// Fused GRU scan (T=4) + per-step QKV projection, f32x2 packed FMA.
// ---------------------------------------------------------------------------
__global__ __launch_bounds__(128)
void k_gru_qkv(const float* __restrict__ h0, const float* __restrict__ x,
               const uint32_t* __restrict__ dones,
               const float* __restrict__ Wi, const float* __restrict__ bi,
               const float* __restrict__ Wh, const float* __restrict__ bhn,
               const float* __restrict__ Wq, const float* __restrict__ bq,
               const float* __restrict__ Wk, const float* __restrict__ bk,
               const float* __restrict__ Wv, const float* __restrict__ bv,
               float* __restrict__ hfin_out)
{
    extern __shared__ float smem[];
    float* sWh   = smem;              // 12288
    float* sWi   = sWh + 12288;       // 768
    float* sWqkv = sWi + 768;         // 12288
    float* sbi   = sWqkv + 12288;     // 192
    float* sbqkv = sbi + 192;         // 192
    float* sbhn  = sbqkv + 192;       // 64

    for (int i = threadIdx.x; i < 12288; i += 128) sWh[i] = Wh[i];
    for (int i = threadIdx.x; i < 768;   i += 128) sWi[i] = Wi[i];
    for (int i = threadIdx.x; i < 12288; i += 128) {
        int j = i / 192, e = i % 192;
        sWqkv[i] = (e < 64) ? Wq[j*64 + e] : (e < 128) ? Wk[j*64 + e - 64] : Wv[j*64 + e - 128];
    }
    for (int i = threadIdx.x; i < 192; i += 128) sbi[i] = bi[i];
    for (int i = threadIdx.x; i < 192; i += 128)
        sbqkv[i] = (i < 64) ? bq[i] : (i < 128) ? bk[i - 64] : bv[i - 128];
    for (int i = threadIdx.x; i < 64; i += 128) sbhn[i] = bhn[i];
    __syncthreads();

    const float4* sWh4   = (const float4*)sWh;
    const float4* sWi4   = (const float4*)sWi;
    const float4* sbi4   = (const float4*)sbi;
    const float4* sbqkv4 = (const float4*)sbqkv;
    const float4* sbhn4  = (const float4*)sbhn;
    const ulonglong2* sWh2   = (const ulonglong2*)sWh;
    const ulonglong2* sWqkv2 = (const ulonglong2*)sWqkv;

    int gid = blockIdx.x * 128 + threadIdx.x;
    int b = gid >> 14;

    float h[64];
    {
        const float4* h04 = (const float4*)(h0 + (size_t)gid * 64);
        #pragma unroll
        for (int j = 0; j < 16; j++) {
            float4 v = h04[j];
            h[4*j] = v.x; h[4*j+1] = v.y; h[4*j+2] = v.z; h[4*j+3] = v.w;
        }
    }

    #pragma unroll 1
    for (int t = 0; t < Tt; t++) {
        if (dones[t * Bb + b] != 0u) {
            #pragma unroll
            for (int j = 0; j < 64; j++) h[j] = 0.f;
        }
        float4 xt4 = ((const float4*)x)[(size_t)t * BNc + gid];
        float xt[4] = {xt4.x, xt4.y, xt4.z, xt4.w};

        float hn[64];
        #pragma unroll
        for (int kk = 0; kk < 16; kk++) {
            unsigned long long ar0=0ULL, ar1=0ULL, az0=0ULL, az1=0ULL, an0=0ULL, an1=0ULL;
            #pragma unroll
            for (int j = 0; j < 64; j++) {
                unsigned long long h2 = packdup(h[j]);
                ulonglong2 wr = sWh2[j*48 + kk];
                ulonglong2 wz = sWh2[j*48 + 16 + kk];
                ulonglong2 wn = sWh2[j*48 + 32 + kk];
                ffma2(ar0, h2, wr.x); ffma2(ar1, h2, wr.y);
                ffma2(az0, h2, wz.x); ffma2(az1, h2, wz.y);
                ffma2(an0, h2, wn.x); ffma2(an1, h2, wn.y);
            }
            float2 arl = unpack2(ar0), arh = unpack2(ar1);
            float2 azl = unpack2(az0), azh = unpack2(az1);
            float2 anl = unpack2(an0), anh = unpack2(an1);
            float4 ar = {arl.x, arl.y, arh.x, arh.y};
            float4 az = {azl.x, azl.y, azh.x, azh.y};
            float4 an = {anl.x, anl.y, anh.x, anh.y};

            float4 gr = sbi4[kk], gz = sbi4[16 + kk], gn = sbi4[32 + kk];
            #pragma unroll
            for (int d = 0; d < 4; d++) {
                float xd = xt[d];
                fma4_(gr, xd, sWi4[d*48 + kk]);
                fma4_(gz, xd, sWi4[d*48 + 16 + kk]);
                fma4_(gn, xd, sWi4[d*48 + 32 + kk]);
            }
            float4 bn4 = sbhn4[kk];
            float r, z, nv;
            r = sigmoidf_(gr.x + ar.x); z = sigmoidf_(gz.x + az.x);
            nv = tanhf(gn.x + r * (an.x + bn4.x));
            hn[4*kk+0] = (1.f - z) * nv + z * h[4*kk+0];
            r = sigmoidf_(gr.y + ar.y); z = sigmoidf_(gz.y + az.y);
            nv = tanhf(gn.y + r * (an.y + bn4.y));
            hn[4*kk+1] = (1.f - z) * nv + z * h[4*kk+1];
            r = sigmoidf_(gr.z + ar.z); z = sigmoidf_(gz.z + az.z);
            nv = tanhf(gn.z + r * (an.z + bn4.z));
            hn[4*kk+2] = (1.f - z) * nv + z * h[4*kk+2];
            r = sigmoidf_(gr.w + ar.w); z = sigmoidf_(gz.w + az.w);
            nv = tanhf(gn.w + r * (an.w + bn4.w));
            hn[4*kk+3] = (1.f - z) * nv + z * h[4*kk+3];
        }
        #pragma unroll
        for (int j = 0; j < 64; j++) h[j] = hn[j];

        // QKV projection (f32x2)
        float4* out = (float4*)(g_qkv + ((size_t)t * BNc + gid) * H3c);
        #pragma unroll 1
        for (int kk = 0; kk < 48; kk++) {
            float4 bia = sbqkv4[kk];
            unsigned long long a0 = pack2(bia.x, bia.y);
            unsigned long long a1 = pack2(bia.z, bia.w);
            #pragma unroll
            for (int j = 0; j < 64; j++) {
                unsigned long long h2 = packdup(h[j]);
                ulonglong2 w = sWqkv2[j*48 + kk];
                ffma2(a0, h2, w.x); ffma2(a1, h2, w.y);
            }
            float2 lo = unpack2(a0), hi = unpack2(a1);
            out[kk] = make_float4(lo.x, lo.y, hi.x, hi.y);
        }
    }

    float4* ho = (float4*)(hfin_out + (size_t)gid * 64);
    #pragma unroll
    for (int j = 0; j < 16; j++)
        ho[j] = make_float4(h[4*j], h[4*j+1], h[4*j+2], h[4*j+3]);
}

// ---------------------------------------------------------------------------
// Attention per (t,b,f) (unchanged).
// ---------------------------------------------------------------------------
__global__ __launch_bounds__(256)
void k_attn(const int* __restrict__ indices)
{
    __shared__ __align__(16) float sR[8][3][192];
    __shared__ __align__(16) float sO[8][3][64];

    int warp = threadIdx.x >> 5, lane = threadIdx.x & 31;
    int inst = blockIdx.x * 8 + warp;
    int tb = inst >> 14;
    int f  = inst & 16383;

    int idx[3] = {__ldg(&indices[f*3]), __ldg(&indices[f*3+1]), __ldg(&indices[f*3+2])};

    const float* base = g_qkv + (size_t)tb * Nn * H3c;
    #pragma unroll
    for (int k = 0; k < 3; k++) {
        const float* row = base + (size_t)idx[k] * H3c;
        #pragma unroll
        for (int u = 0; u < 6; u++) sR[warp][k][u*32 + lane] = row[u*32 + lane];
    }
    __syncwarp();

    if (lane < 12) {
        int qr = lane >> 2, hh = lane & 3;
        const float* q = &sR[warp][qr][hh * 16];
        float l[3];
        #pragma unroll
        for (int kr = 0; kr < 3; kr++) {
            const float* kv = &sR[warp][kr][64 + hh * 16];
            float s = 0.f;
            #pragma unroll
            for (int d = 0; d < 16; d++) s += q[d] * kv[d];
            l[kr] = s * 0.25f;
        }
        float m = fmaxf(l[0], fmaxf(l[1], l[2]));
        float e0 = expf(l[0] - m), e1 = expf(l[1] - m), e2 = expf(l[2] - m);
        float inv = 1.f / (e0 + e1 + e2);
        e0 *= inv; e1 *= inv; e2 *= inv;
        const float* v0 = &sR[warp][0][128 + hh * 16];
        const float* v1 = &sR[warp][1][128 + hh * 16];
        const float* v2 = &sR[warp][2][128 + hh * 16];
        #pragma unroll
        for (int d = 0; d < 16; d++)
            sO[warp][qr][hh*16 + d] = e0 * v0[d] + e1 * v1[d] + e2 * v2[d];
    }
    __syncwarp();

    float4* yo = (float4*)g_yo + (size_t)tb * Nn * 16;
    if (lane < 16) {
        #pragma unroll
        for (int k = 0; k < 3; k++) {
            float4 v = ((const float4*)sO[warp][k])[lane];
            atomicAdd(&yo[(size_t)idx[k] * 16 + lane], v);
        }
    }
}

// ---------------------------------------------------------------------------
// Segment sums for the value head (256 blocks; partials via global atomics).
// ---------------------------------------------------------------------------
__global__ __launch_bounds__(256)
void k_sum(const float* __restrict__ nnz)
{
    __shared__ float red[4][64];
    __shared__ float red0[4];
    int blk = blockIdx.x;        // 0..255
    int g = blk >> 2, chunk = blk & 3;
    int tid = threadIdx.x;
    int r4 = tid >> 6;
    int col = tid & 63;

    float acc = 0.f, acc0 = 0.f;
    int nbase = (g & 3) * 4096;
    const float* yob = g_yo + (size_t)g * 4096 * 64;
    int rend = (chunk + 1) * 1024;
    for (int rr = chunk * 1024 + r4; rr < rend; rr += 4) {
        int n = nbase + rr;
        float inv = 1.f / nnz[n];
        acc += yob[(size_t)rr * 64 + col] * inv;
        if (col == 0) acc0 += (float)g_cnt[n] * inv;
    }
    red[r4][col] = acc;
    if (col == 0) red0[r4] = acc0;
    __syncthreads();
    if (tid < 64)
        atomicAdd(&g_s1[g * 64 + tid], red[0][tid] + red[1][tid] + red[2][tid] + red[3][tid]);
    if (tid == 0)
        atomicAdd(&g_s0[g], red0[0] + red0[1] + red0[2] + red0[3]);
}

// ---------------------------------------------------------------------------
// Logit head: one thread per row; 4 passes of 16 outputs (regs < 128).
// pre[c] = invnnz*(yo . M[:,c]) + cn*invnnz*c1[c] + E[g][c]
// logit  = sum_c relu(pre[c])*W2[c] + b2
// ---------------------------------------------------------------------------
__global__ __launch_bounds__(256, 2)
void k_post(const float* __restrict__ nnz,
            const float* __restrict__ W2, const float* __restrict__ b2,
            float* __restrict__ logit_out)
{
    extern __shared__ float ps[];
    float4* sT4 = (float4*)ps;                 // 256 rows x 17 float4 (pad)
    float*  sM  = ps + 256*17*4;               // 4096
    float*  sc1 = sM + 4096;                   // 64
    float*  sE  = sc1 + 64;                    // 64
    float*  sW2 = sE + 64;                     // 64

    int tid = threadIdx.x;
    int rowbase = blockIdx.x * 256;
    int g = rowbase >> 12;

    const float4* yo4 = (const float4*)g_yo + (size_t)rowbase * 16;
    for (int i = tid; i < 4096; i += 256)
        sT4[(i >> 4) * 17 + (i & 15)] = yo4[i];
    for (int i = tid; i < 4096; i += 256) sM[i] = g_M[i];
    if (tid < 64) { sc1[tid] = g_c1[tid]; sE[tid] = g_E[g*64 + tid]; sW2[tid] = W2[tid]; }
    __syncthreads();

    int row = rowbase + tid;
    int n = row & 16383;
    float inv = 1.f / nnz[n];
    float cninv = (float)g_cnt[n] * inv;

    float yo[64];
    #pragma unroll
    for (int jj = 0; jj < 16; jj++) {
        float4 v = sT4[tid * 17 + jj];
        yo[4*jj] = v.x; yo[4*jj+1] = v.y; yo[4*jj+2] = v.z; yo[4*jj+3] = v.w;
    }

    const ulonglong2* sM2 = (const ulonglong2*)sM;
    float logit = 0.f;
    #pragma unroll 1
    for (int p = 0; p < 4; p++) {              // 4 passes x 16 outputs
        unsigned long long acc[8];
        #pragma unroll
        for (int q = 0; q < 8; q++) acc[q] = 0ULL;
        #pragma unroll
        for (int j = 0; j < 64; j++) {
            unsigned long long y2 = packdup(yo[j]);
            #pragma unroll
            for (int q = 0; q < 4; q++) {
                ulonglong2 w = sM2[j*16 + p*4 + q];
                ffma2(acc[2*q],   y2, w.x);
                ffma2(acc[2*q+1], y2, w.y);
            }
        }
        #pragma unroll
        for (int q = 0; q < 8; q++) {
            float2 v = unpack2(acc[q]);
            int c = p*16 + q*2;
            float pre, r;
            pre = inv*v.x + cninv*sc1[c]   + sE[c];   r = fmaxf(pre, 0.f); logit += r*sW2[c];
            pre = inv*v.y + cninv*sc1[c+1] + sE[c+1]; r = fmaxf(pre, 0.f); logit += r*sW2[c+1];
        }
    }
    logit_out[row] = logit + b2[0];
}

// ---------------------------------------------------------------------------
// Value head
// ---------------------------------------------------------------------------
__global__ void k_value(const float* __restrict__ extra,
                        const float* __restrict__ Wv1, const float* __restrict__ bv1,
                        float* __restrict__ val_out)
{
    __shared__ float sv[64];
    int tid = threadIdx.x;                  // 64 = (tb,kall)
    float acc = 0.f;
    #pragma unroll
    for (int j = 0; j < 64; j++) acc += g_s1[tid*64 + j] * g_wv[j];
    acc += g_s0[tid] * g_bv[0];
    acc *= (1.f / (float)N0c);
    #pragma unroll
    for (int d = 0; d < 4; d++) acc += extra[tid*4 + d] * Wv1[64 + d];
    acc += bv1[0];
    sv[tid] = acc;
    __syncthreads();
    if (tid < 16)
        val_out[tid] = sv[tid*4] + sv[tid*4+1] + sv[tid*4+2] + sv[tid*4+3];
}

// ---------------------------------------------------------------------------
extern "C" void kernel_launch(void* const* d_in, const int* in_sizes, int n_in,
                              void* d_out, int out_size)
{
    const float* h0       = (const float*)d_in[0];
    const float* h_global = (const float*)d_in[1];
    const float* x        = (const float*)d_in[2];
    const float* extra    = (const float*)d_in[3];
    const uint32_t* dones = (const uint32_t*)d_in[4];
    const int*   indices  = (const int*)d_in[5];
    const float* nnz      = (const float*)d_in[6];
    const float* Wi  = (const float*)d_in[7];
    const float* bi  = (const float*)d_in[8];
    const float* Wh  = (const float*)d_in[9];
    const float* bhn = (const float*)d_in[10];
    const float* Wq  = (const float*)d_in[11];
    const float* bq  = (const float*)d_in[12];
    const float* Wk  = (const float*)d_in[13];
    const float* bk  = (const float*)d_in[14];
    const float* Wv  = (const float*)d_in[15];
    const float* bv  = (const float*)d_in[16];
    const float* Wo  = (const float*)d_in[17];
    const float* bo  = (const float*)d_in[18];
    const float* W1  = (const float*)d_in[19];
    const float* b1  = (const float*)d_in[20];
    const float* W2  = (const float*)d_in[21];
    const float* b2  = (const float*)d_in[22];
    const float* Wv1 = (const float*)d_in[23];
    const float* bv1 = (const float*)d_in[24];

    float* out       = (float*)d_out;
    float* out_hfin  = out;
    float* out_hg    = out + OFF_HG;
    float* out_logit = out + OFF_LOGIT;
    float* out_val   = out + OFF_VAL;

    void *yo_ptr, *cnt_ptr, *s1_ptr, *s0_ptr;
    cudaGetSymbolAddress(&yo_ptr,  g_yo);
    cudaGetSymbolAddress(&cnt_ptr, g_cnt);
    cudaGetSymbolAddress(&s1_ptr,  g_s1);
    cudaGetSymbolAddress(&s0_ptr,  g_s0);
    cudaMemsetAsync(yo_ptr,  0, sizeof(float) * (size_t)TBNc * Hh, 0);
    cudaMemsetAsync(cnt_ptr, 0, sizeof(int) * Nn, 0);
    cudaMemsetAsync(s1_ptr,  0, sizeof(float) * 64 * 64, 0);
    cudaMemsetAsync(s0_ptr,  0, sizeof(float) * 64, 0);

    cudaMemcpyAsync(out_hg, h_global, 1024 * sizeof(float), cudaMemcpyDeviceToDevice, 0);

    int smem_gru = (12288 + 768 + 12288 + 192 + 192 + 64) * 4;   // 103168 B
    cudaFuncSetAttribute(k_gru_qkv, cudaFuncAttributeMaxDynamicSharedMemorySize, smem_gru);
    int smem_post = (256*17*4 + 4096 + 64 + 64 + 64) * 4;         // 87040 B
    cudaFuncSetAttribute(k_post, cudaFuncAttributeMaxDynamicSharedMemorySize, smem_post);

    k_count<<<(Ff * ORD + 255) / 256, 256>>>(indices);
    k_prep<<<32, 256>>>(Wo, bo, W1, b1, Wv1, extra);
    k_gru_qkv<<<BNc / 128, 128, smem_gru>>>(h0, x, dones, Wi, bi, Wh, bhn,
                                            Wq, bq, Wk, bk, Wv, bv, out_hfin);
    k_attn<<<TBc * Ff / 8, 256>>>(indices);
    k_sum<<<256, 256>>>(nnz);
    k_post<<<TBNc / 256, 256, smem_post>>>(nnz, W2, b2, out_logit);
    k_value<<<1, 64>>>(extra, Wv1, bv1, out_val);
}

// round 5
// speedup vs baseline: 1.4661x; 1.1155x over previous
#include <cuda_runtime.h>
#include <math.h>
#include <stdint.h>

// Problem constants
#define Tt   4
#define Bb   4
#define Nn   16384
#define KALLc 4
#define Ff   16384
#define ORD  3
#define Hh   64
#define N0c  4096

#define TBc  (Tt*Bb)        // 16
#define BNc  (Bb*Nn)        // 65536
#define TBNc (TBc*Nn)       // 262144
#define H3c  (3*Hh)         // 192

// Output layout: h_fin [B,N,H] | h_global [B,K,64] | logit [T,B,N] | value [T,B]
#define OFF_HG    4194304
#define OFF_LOGIT (OFF_HG + 1024)
#define OFF_VAL   (OFF_LOGIT + 262144)

// Scratch
__device__ float g_h  [TBNc * Hh];    // [T,B,N,64] hidden states per step (64 MiB)
__device__ float g_qkv[TBNc * H3c];   // [T,B,N,192]
__device__ float g_yo [TBNc * Hh];    // [T,B,N,64]
__device__ int   g_cnt[Nn];
__device__ float g_M  [64*64];        // Wo @ W1[:64]
__device__ float g_c1 [64];           // bo @ W1[:64]
__device__ float g_E  [64*64];        // per (tb,kall): b1 + extra@W1[64:]
__device__ float g_wv [64];           // Wo @ Wv1[:64]
__device__ float g_bv [1];            // bo @ Wv1[:64]
__device__ float g_s1 [64*64];        // per (tb,kall): sum_n yo*invnnz
__device__ float g_s0 [64];           // per (tb,kall): sum_n cnt*invnnz

__device__ __forceinline__ float sigmoidf_(float v) { return 1.f / (1.f + expf(-v)); }
__device__ __forceinline__ void fma4_(float4& a, float s, float4 w) {
    a.x += s * w.x; a.y += s * w.y; a.z += s * w.z; a.w += s * w.w;
}

// ---- packed fp32 helpers (fma.rn.f32x2) ----
__device__ __forceinline__ unsigned long long packdup(float v) {
    unsigned long long r;
    asm("mov.b64 %0, {%1, %1};" : "=l"(r) : "f"(v));
    return r;
}
__device__ __forceinline__ unsigned long long pack2(float a, float b) {
    unsigned long long r;
    asm("mov.b64 %0, {%1, %2};" : "=l"(r) : "f"(a), "f"(b));
    return r;
}
__device__ __forceinline__ void ffma2(unsigned long long& acc,
                                      unsigned long long a, unsigned long long b) {
    asm("fma.rn.f32x2 %0, %1, %2, %0;" : "+l"(acc) : "l"(a), "l"(b));
}
__device__ __forceinline__ float2 unpack2(unsigned long long v) {
    float lo, hi;
    asm("mov.b64 {%0, %1}, %2;" : "=f"(lo), "=f"(hi) : "l"(v));
    return make_float2(lo, hi);
}

// ---------------------------------------------------------------------------
__global__ void k_count(const int* __restrict__ indices) {
    int i = blockIdx.x * 256 + threadIdx.x;
    if (i < Ff * ORD) atomicAdd(&g_cnt[indices[i]], 1);
}

// ---------------------------------------------------------------------------
__global__ void k_prep(const float* __restrict__ Wo, const float* __restrict__ bo,
                       const float* __restrict__ W1, const float* __restrict__ b1,
                       const float* __restrict__ Wv1,
                       const float* __restrict__ extra)
{
    int o = blockIdx.x * 256 + threadIdx.x;   // grid 32 x 256 = 8192
    if (o < 4096) {
        int j = o >> 6, c = o & 63;
        float s = 0.f;
        #pragma unroll
        for (int h = 0; h < 64; h++) s += Wo[j*64 + h] * W1[h*64 + c];
        g_M[o] = s;
    } else {
        int e = o - 4096;
        int g = e >> 6, c = e & 63;
        float s = b1[c];
        #pragma unroll
        for (int d = 0; d < 4; d++) s += extra[g*4 + d] * W1[(64 + d)*64 + c];
        g_E[e] = s;
    }
    if (blockIdx.x == 0 && threadIdx.x < 64) {
        int tid = threadIdx.x;
        float s = 0.f, w = 0.f;
        #pragma unroll
        for (int h = 0; h < 64; h++) {
            s += bo[h] * W1[h*64 + tid];
            w += Wo[tid*64 + h] * Wv1[h];
        }
        g_c1[tid] = s;
        g_wv[tid] = w;
        if (tid == 0) {
            float bvv = 0.f;
            #pragma unroll
            for (int h = 0; h < 64; h++) bvv += bo[h] * Wv1[h];
            g_bv[0] = bvv;
        }
    }
}

// ---------------------------------------------------------------------------
// GRU scan only (T=4). One thread per (b,n). smem 53KB -> 3 blocks/SM.
// Writes h_t for every step to g_h, final h to hfin_out.
// ---------------------------------------------------------------------------
__global__ __launch_bounds__(128, 3)
void k_gru(const float* __restrict__ h0, const float* __restrict__ x,
           const uint32_t* __restrict__ dones,
           const float* __restrict__ Wi, const float* __restrict__ bi,
           const float* __restrict__ Wh, const float* __restrict__ bhn,
           float* __restrict__ hfin_out)
{
    extern __shared__ float smem[];
    float* sWh  = smem;              // 12288
    float* sWi  = sWh + 12288;       // 768
    float* sbi  = sWi + 768;         // 192
    float* sbhn = sbi + 192;         // 64

    for (int i = threadIdx.x; i < 12288; i += 128) sWh[i] = Wh[i];
    for (int i = threadIdx.x; i < 768;   i += 128) sWi[i] = Wi[i];
    for (int i = threadIdx.x; i < 192;   i += 128) sbi[i] = bi[i];
    for (int i = threadIdx.x; i < 64;    i += 128) sbhn[i] = bhn[i];
    __syncthreads();

    const float4* sWi4  = (const float4*)sWi;
    const float4* sbi4  = (const float4*)sbi;
    const float4* sbhn4 = (const float4*)sbhn;
    const ulonglong2* sWh2 = (const ulonglong2*)sWh;

    int gid = blockIdx.x * 128 + threadIdx.x;
    int b = gid >> 14;

    float h[64];
    {
        const float4* h04 = (const float4*)(h0 + (size_t)gid * 64);
        #pragma unroll
        for (int j = 0; j < 16; j++) {
            float4 v = h04[j];
            h[4*j] = v.x; h[4*j+1] = v.y; h[4*j+2] = v.z; h[4*j+3] = v.w;
        }
    }

    #pragma unroll 1
    for (int t = 0; t < Tt; t++) {
        if (dones[t * Bb + b] != 0u) {
            #pragma unroll
            for (int j = 0; j < 64; j++) h[j] = 0.f;
        }
        float4 xt4 = ((const float4*)x)[(size_t)t * BNc + gid];
        float xt[4] = {xt4.x, xt4.y, xt4.z, xt4.w};

        float hn[64];
        #pragma unroll
        for (int kk = 0; kk < 16; kk++) {
            unsigned long long ar0=0ULL, ar1=0ULL, az0=0ULL, az1=0ULL, an0=0ULL, an1=0ULL;
            #pragma unroll
            for (int j = 0; j < 64; j++) {
                unsigned long long h2 = packdup(h[j]);
                ulonglong2 wr = sWh2[j*48 + kk];
                ulonglong2 wz = sWh2[j*48 + 16 + kk];
                ulonglong2 wn = sWh2[j*48 + 32 + kk];
                ffma2(ar0, h2, wr.x); ffma2(ar1, h2, wr.y);
                ffma2(az0, h2, wz.x); ffma2(az1, h2, wz.y);
                ffma2(an0, h2, wn.x); ffma2(an1, h2, wn.y);
            }
            float2 arl = unpack2(ar0), arh = unpack2(ar1);
            float2 azl = unpack2(az0), azh = unpack2(az1);
            float2 anl = unpack2(an0), anh = unpack2(an1);
            float4 ar = {arl.x, arl.y, arh.x, arh.y};
            float4 az = {azl.x, azl.y, azh.x, azh.y};
            float4 an = {anl.x, anl.y, anh.x, anh.y};

            float4 gr = sbi4[kk], gz = sbi4[16 + kk], gn = sbi4[32 + kk];
            #pragma unroll
            for (int d = 0; d < 4; d++) {
                float xd = xt[d];
                fma4_(gr, xd, sWi4[d*48 + kk]);
                fma4_(gz, xd, sWi4[d*48 + 16 + kk]);
                fma4_(gn, xd, sWi4[d*48 + 32 + kk]);
            }
            float4 bn4 = sbhn4[kk];
            float r, z, nv;
            r = sigmoidf_(gr.x + ar.x); z = sigmoidf_(gz.x + az.x);
            nv = tanhf(gn.x + r * (an.x + bn4.x));
            hn[4*kk+0] = (1.f - z) * nv + z * h[4*kk+0];
            r = sigmoidf_(gr.y + ar.y); z = sigmoidf_(gz.y + az.y);
            nv = tanhf(gn.y + r * (an.y + bn4.y));
            hn[4*kk+1] = (1.f - z) * nv + z * h[4*kk+1];
            r = sigmoidf_(gr.z + ar.z); z = sigmoidf_(gz.z + az.z);
            nv = tanhf(gn.z + r * (an.z + bn4.z));
            hn[4*kk+2] = (1.f - z) * nv + z * h[4*kk+2];
            r = sigmoidf_(gr.w + ar.w); z = sigmoidf_(gz.w + az.w);
            nv = tanhf(gn.w + r * (an.w + bn4.w));
            hn[4*kk+3] = (1.f - z) * nv + z * h[4*kk+3];
        }
        #pragma unroll
        for (int j = 0; j < 64; j++) h[j] = hn[j];

        float4* hout = (float4*)(g_h + ((size_t)t * BNc + gid) * 64);
        #pragma unroll
        for (int j = 0; j < 16; j++)
            hout[j] = make_float4(h[4*j], h[4*j+1], h[4*j+2], h[4*j+3]);
    }

    float4* ho = (float4*)(hfin_out + (size_t)gid * 64);
    #pragma unroll
    for (int j = 0; j < 16; j++)
        ho[j] = make_float4(h[4*j], h[4*j+1], h[4*j+2], h[4*j+3]);
}

// ---------------------------------------------------------------------------
// QKV projection: [262144 x 64] @ [64 x 192] GEMV per row. One thread per row.
// 512-thread blocks, ~16 warps/SM. 6 register tiles of 32 outputs.
// ---------------------------------------------------------------------------
__global__ __launch_bounds__(512)
void k_qkv(const float* __restrict__ Wq, const float* __restrict__ bq,
           const float* __restrict__ Wk, const float* __restrict__ bk,
           const float* __restrict__ Wv, const float* __restrict__ bv)
{
    extern __shared__ float qs[];
    float* sW = qs;            // 12288 (64 x 192, q|k|v interleaved per input j)
    float* sb = sW + 12288;    // 192

    for (int i = threadIdx.x; i < 12288; i += 512) {
        int j = i / 192, e = i % 192;
        sW[i] = (e < 64) ? Wq[j*64 + e] : (e < 128) ? Wk[j*64 + e - 64] : Wv[j*64 + e - 128];
    }
    for (int i = threadIdx.x; i < 192; i += 512)
        sb[i] = (i < 64) ? bq[i] : (i < 128) ? bk[i - 64] : bv[i - 128];
    __syncthreads();

    const ulonglong2* sW2 = (const ulonglong2*)sW;   // [j][48] float4-chunks
    const float4*     sb4 = (const float4*)sb;

    size_t r = (size_t)blockIdx.x * 512 + threadIdx.x;   // row < 262144

    float h[64];
    {
        const float4* h4 = (const float4*)(g_h + r * 64);
        #pragma unroll
        for (int j = 0; j < 16; j++) {
            float4 v = h4[j];
            h[4*j] = v.x; h[4*j+1] = v.y; h[4*j+2] = v.z; h[4*j+3] = v.w;
        }
    }

    float4* out = (float4*)(g_qkv + r * H3c);
    #pragma unroll 1
    for (int tile = 0; tile < 6; tile++) {       // 6 tiles x 8 quads = 48 quads
        unsigned long long acc[16];
        #pragma unroll
        for (int q = 0; q < 8; q++) {
            float4 bb = sb4[tile*8 + q];
            acc[2*q]   = pack2(bb.x, bb.y);
            acc[2*q+1] = pack2(bb.z, bb.w);
        }
        #pragma unroll
        for (int j = 0; j < 64; j++) {
            unsigned long long h2 = packdup(h[j]);
            #pragma unroll
            for (int q = 0; q < 8; q++) {
                ulonglong2 w = sW2[j*48 + tile*8 + q];
                ffma2(acc[2*q],   h2, w.x);
                ffma2(acc[2*q+1], h2, w.y);
            }
        }
        #pragma unroll
        for (int q = 0; q < 8; q++) {
            float2 lo = unpack2(acc[2*q]), hi = unpack2(acc[2*q+1]);
            out[tile*8 + q] = make_float4(lo.x, lo.y, hi.x, hi.y);
        }
    }
}

// ---------------------------------------------------------------------------
// Attention per (t,b,f) (unchanged).
// ---------------------------------------------------------------------------
__global__ __launch_bounds__(256)
void k_attn(const int* __restrict__ indices)
{
    __shared__ __align__(16) float sR[8][3][192];
    __shared__ __align__(16) float sO[8][3][64];

    int warp = threadIdx.x >> 5, lane = threadIdx.x & 31;
    int inst = blockIdx.x * 8 + warp;
    int tb = inst >> 14;
    int f  = inst & 16383;

    int idx[3] = {__ldg(&indices[f*3]), __ldg(&indices[f*3+1]), __ldg(&indices[f*3+2])};

    const float* base = g_qkv + (size_t)tb * Nn * H3c;
    #pragma unroll
    for (int k = 0; k < 3; k++) {
        const float* row = base + (size_t)idx[k] * H3c;
        #pragma unroll
        for (int u = 0; u < 6; u++) sR[warp][k][u*32 + lane] = row[u*32 + lane];
    }
    __syncwarp();

    if (lane < 12) {
        int qr = lane >> 2, hh = lane & 3;
        const float* q = &sR[warp][qr][hh * 16];
        float l[3];
        #pragma unroll
        for (int kr = 0; kr < 3; kr++) {
            const float* kv = &sR[warp][kr][64 + hh * 16];
            float s = 0.f;
            #pragma unroll
            for (int d = 0; d < 16; d++) s += q[d] * kv[d];
            l[kr] = s * 0.25f;
        }
        float m = fmaxf(l[0], fmaxf(l[1], l[2]));
        float e0 = expf(l[0] - m), e1 = expf(l[1] - m), e2 = expf(l[2] - m);
        float inv = 1.f / (e0 + e1 + e2);
        e0 *= inv; e1 *= inv; e2 *= inv;
        const float* v0 = &sR[warp][0][128 + hh * 16];
        const float* v1 = &sR[warp][1][128 + hh * 16];
        const float* v2 = &sR[warp][2][128 + hh * 16];
        #pragma unroll
        for (int d = 0; d < 16; d++)
            sO[warp][qr][hh*16 + d] = e0 * v0[d] + e1 * v1[d] + e2 * v2[d];
    }
    __syncwarp();

    float4* yo = (float4*)g_yo + (size_t)tb * Nn * 16;
    if (lane < 16) {
        #pragma unroll
        for (int k = 0; k < 3; k++) {
            float4 v = ((const float4*)sO[warp][k])[lane];
            atomicAdd(&yo[(size_t)idx[k] * 16 + lane], v);
        }
    }
}

// ---------------------------------------------------------------------------
__global__ __launch_bounds__(256)
void k_sum(const float* __restrict__ nnz)
{
    __shared__ float red[4][64];
    __shared__ float red0[4];
    int blk = blockIdx.x;        // 0..255
    int g = blk >> 2, chunk = blk & 3;
    int tid = threadIdx.x;
    int r4 = tid >> 6;
    int col = tid & 63;

    float acc = 0.f, acc0 = 0.f;
    int nbase = (g & 3) * 4096;
    const float* yob = g_yo + (size_t)g * 4096 * 64;
    int rend = (chunk + 1) * 1024;
    for (int rr = chunk * 1024 + r4; rr < rend; rr += 4) {
        int n = nbase + rr;
        float inv = 1.f / nnz[n];
        acc += yob[(size_t)rr * 64 + col] * inv;
        if (col == 0) acc0 += (float)g_cnt[n] * inv;
    }
    red[r4][col] = acc;
    if (col == 0) red0[r4] = acc0;
    __syncthreads();
    if (tid < 64)
        atomicAdd(&g_s1[g * 64 + tid], red[0][tid] + red[1][tid] + red[2][tid] + red[3][tid]);
    if (tid == 0)
        atomicAdd(&g_s0[g], red0[0] + red0[1] + red0[2] + red0[3]);
}

// ---------------------------------------------------------------------------
// Logit head: one thread per row; 8 passes of 8 outputs (regs ~92, no spill).
// ---------------------------------------------------------------------------
__global__ __launch_bounds__(256, 2)
void k_post(const float* __restrict__ nnz,
            const float* __restrict__ W2, const float* __restrict__ b2,
            float* __restrict__ logit_out)
{
    extern __shared__ float ps[];
    float4* sT4 = (float4*)ps;                 // 256 rows x 17 float4 (pad)
    float*  sM  = ps + 256*17*4;               // 4096
    float*  sc1 = sM + 4096;                   // 64
    float*  sE  = sc1 + 64;                    // 64
    float*  sW2 = sE + 64;                     // 64

    int tid = threadIdx.x;
    int rowbase = blockIdx.x * 256;
    int g = rowbase >> 12;

    const float4* yo4 = (const float4*)g_yo + (size_t)rowbase * 16;
    for (int i = tid; i < 4096; i += 256)
        sT4[(i >> 4) * 17 + (i & 15)] = yo4[i];
    for (int i = tid; i < 4096; i += 256) sM[i] = g_M[i];
    if (tid < 64) { sc1[tid] = g_c1[tid]; sE[tid] = g_E[g*64 + tid]; sW2[tid] = W2[tid]; }
    __syncthreads();

    int row = rowbase + tid;
    int n = row & 16383;
    float inv = 1.f / nnz[n];
    float cninv = (float)g_cnt[n] * inv;

    float yo[64];
    #pragma unroll
    for (int jj = 0; jj < 16; jj++) {
        float4 v = sT4[tid * 17 + jj];
        yo[4*jj] = v.x; yo[4*jj+1] = v.y; yo[4*jj+2] = v.z; yo[4*jj+3] = v.w;
    }

    const ulonglong2* sM2 = (const ulonglong2*)sM;
    float logit = 0.f;
    #pragma unroll 1
    for (int p = 0; p < 8; p++) {              // 8 passes x 8 outputs
        unsigned long long acc[4] = {0ULL, 0ULL, 0ULL, 0ULL};
        #pragma unroll
        for (int j = 0; j < 64; j++) {
            unsigned long long y2 = packdup(yo[j]);
            ulonglong2 w0 = sM2[j*16 + p*2];
            ulonglong2 w1 = sM2[j*16 + p*2 + 1];
            ffma2(acc[0], y2, w0.x);
            ffma2(acc[1], y2, w0.y);
            ffma2(acc[2], y2, w1.x);
            ffma2(acc[3], y2, w1.y);
        }
        #pragma unroll
        for (int q = 0; q < 4; q++) {
            float2 v = unpack2(acc[q]);
            int c = p*8 + q*2;
            float pre, rr;
            pre = inv*v.x + cninv*sc1[c]   + sE[c];   rr = fmaxf(pre, 0.f); logit += rr*sW2[c];
            pre = inv*v.y + cninv*sc1[c+1] + sE[c+1]; rr = fmaxf(pre, 0.f); logit += rr*sW2[c+1];
        }
    }
    logit_out[row] = logit + b2[0];
}

// ---------------------------------------------------------------------------
__global__ void k_value(const float* __restrict__ extra,
                        const float* __restrict__ Wv1, const float* __restrict__ bv1,
                        float* __restrict__ val_out)
{
    __shared__ float sv[64];
    int tid = threadIdx.x;                  // 64 = (tb,kall)
    float acc = 0.f;
    #pragma unroll
    for (int j = 0; j < 64; j++) acc += g_s1[tid*64 + j] * g_wv[j];
    acc += g_s0[tid] * g_bv[0];
    acc *= (1.f / (float)N0c);
    #pragma unroll
    for (int d = 0; d < 4; d++) acc += extra[tid*4 + d] * Wv1[64 + d];
    acc += bv1[0];
    sv[tid] = acc;
    __syncthreads();
    if (tid < 16)
        val_out[tid] = sv[tid*4] + sv[tid*4+1] + sv[tid*4+2] + sv[tid*4+3];
}

// ---------------------------------------------------------------------------
extern "C" void kernel_launch(void* const* d_in, const int* in_sizes, int n_in,
                              void* d_out, int out_size)
{
    const float* h0       = (const float*)d_in[0];
    const float* h_global = (const float*)d_in[1];
    const float* x        = (const float*)d_in[2];
    const float* extra    = (const float*)d_in[3];
    const uint32_t* dones = (const uint32_t*)d_in[4];
    const int*   indices  = (const int*)d_in[5];
    const float* nnz      = (const float*)d_in[6];
    const float* Wi  = (const float*)d_in[7];
    const float* bi  = (const float*)d_in[8];
    const float* Wh  = (const float*)d_in[9];
    const float* bhn = (const float*)d_in[10];
    const float* Wq  = (const float*)d_in[11];
    const float* bq  = (const float*)d_in[12];
    const float* Wk  = (const float*)d_in[13];
    const float* bk  = (const float*)d_in[14];
    const float* Wv  = (const float*)d_in[15];
    const float* bv  = (const float*)d_in[16];
    const float* Wo  = (const float*)d_in[17];
    const float* bo  = (const float*)d_in[18];
    const float* W1  = (const float*)d_in[19];
    const float* b1  = (const float*)d_in[20];
    const float* W2  = (const float*)d_in[21];
    const float* b2  = (const float*)d_in[22];
    const float* Wv1 = (const float*)d_in[23];
    const float* bv1 = (const float*)d_in[24];

    float* out       = (float*)d_out;
    float* out_hfin  = out;
    float* out_hg    = out + OFF_HG;
    float* out_logit = out + OFF_LOGIT;
    float* out_val   = out + OFF_VAL;

    void *yo_ptr, *cnt_ptr, *s1_ptr, *s0_ptr;
    cudaGetSymbolAddress(&yo_ptr,  g_yo);
    cudaGetSymbolAddress(&cnt_ptr, g_cnt);
    cudaGetSymbolAddress(&s1_ptr,  g_s1);
    cudaGetSymbolAddress(&s0_ptr,  g_s0);
    cudaMemsetAsync(yo_ptr,  0, sizeof(float) * (size_t)TBNc * Hh, 0);
    cudaMemsetAsync(cnt_ptr, 0, sizeof(int) * Nn, 0);
    cudaMemsetAsync(s1_ptr,  0, sizeof(float) * 64 * 64, 0);
    cudaMemsetAsync(s0_ptr,  0, sizeof(float) * 64, 0);

    cudaMemcpyAsync(out_hg, h_global, 1024 * sizeof(float), cudaMemcpyDeviceToDevice, 0);

    int smem_gru  = (12288 + 768 + 192 + 64) * 4;                 // 53248 B
    cudaFuncSetAttribute(k_gru, cudaFuncAttributeMaxDynamicSharedMemorySize, smem_gru);
    int smem_qkv  = (12288 + 192) * 4;                             // 49920 B
    cudaFuncSetAttribute(k_qkv, cudaFuncAttributeMaxDynamicSharedMemorySize, smem_qkv);
    int smem_post = (256*17*4 + 4096 + 64 + 64 + 64) * 4;          // 87040 B
    cudaFuncSetAttribute(k_post, cudaFuncAttributeMaxDynamicSharedMemorySize, smem_post);

    k_count<<<(Ff * ORD + 255) / 256, 256>>>(indices);
    k_prep<<<32, 256>>>(Wo, bo, W1, b1, Wv1, extra);
    k_gru<<<BNc / 128, 128, smem_gru>>>(h0, x, dones, Wi, bi, Wh, bhn, out_hfin);
    k_qkv<<<TBNc / 512, 512, smem_qkv>>>(Wq, bq, Wk, bk, Wv, bv);
    k_attn<<<TBc * Ff / 8, 256>>>(indices);
    k_sum<<<256, 256>>>(nnz);
    k_post<<<TBNc / 256, 256, smem_post>>>(nnz, W2, b2, out_logit);
    k_value<<<1, 64>>>(extra, Wv1, bv1, out_val);
}